// round 13
// baseline (speedup 1.0000x reference)
#include <cuda_runtime.h>
#include <math.h>

typedef unsigned long long ull;

#define D        64
#define KCODES   1024
#define KC       128         // codes per chunk (one warp covers all 128 via 32 lanes x 4 codes)
#define MT       64          // rows per block (8 warps x 8 rows)
#define NTHREADS 256
#define WX       132         // dup-x tile row width (floats): 128 data + 4 pad; 16B-aligned rows
#define WC       132         // code tile row width (floats): 32 granules (128 floats) + 1 pad granule

// scratch (no cudaMalloc allowed)
__device__ int   g_counts[KCODES];
__device__ float g_loss[2];   // [0] = sum (qst-x)^2, [1] = sum (q-x)^2
__device__ unsigned g_done;

__device__ __forceinline__ ull pack2(float lo, float hi) {
    ull r;
    asm("mov.b64 %0, {%1, %2};" : "=l"(r) : "f"(lo), "f"(hi));
    return r;
}
__device__ __forceinline__ ull fma2(ull a, ull b, ull c) {
    ull d;
    asm("fma.rn.f32x2 %0, %1, %2, %3;" : "=l"(d) : "l"(a), "l"(b), "l"(c));
    return d;
}
__device__ __forceinline__ float lo32(ull v) { return __uint_as_float((unsigned)(v & 0xffffffffull)); }
__device__ __forceinline__ float hi32(ull v) { return __uint_as_float((unsigned)(v >> 32)); }

// ---------------------------------------------------------------------------
// fused: distance GEMM + argmin + quantize(ST) + losses + counts + finalize.
// warp = 8 rows x 128 codes: per d-iter the code side is ONE LDS.128 with all
// 32 lanes distinct (codes 4L..4L+3 via additive granule swizzle (g+2d)&31,
// conflict-free both on store AND load) and the x side is 4 broadcast LDS.128
// of dup-stored rows. 16 packed f32x2 FMA vs ~8 crossbar wavefronts.
// ---------------------------------------------------------------------------
__global__ void __launch_bounds__(NTHREADS, 2)
vq_fused(const float* __restrict__ xin, const float* __restrict__ cb,
         float* __restrict__ outq, float* __restrict__ outt,
         float* __restrict__ outs, float inv_ND, float invN) {
    extern __shared__ float smem[];
    float* sx2 = smem;                    // [D][WX] dup-stored x tile (d-major)
    float* sc  = smem + D * WX;           // [D][WC] code chunk, granule-swizzled
    float* scn = smem + 2 * D * WX;       // [KC] code norms of chunk  (WX==WC)
    __shared__ int s_last;

    const int tid  = threadIdx.x;
    const int lane = tid & 31;
    const int warp = tid >> 5;            // 8 warps, warp w owns rows 8w..8w+7
    const int rb2  = warp * 16;           // dup-float offset of warp's row base
    const int row0 = blockIdx.x * MT;

    // ---- load x tile, duplicate-stored transposed (coalesced global read) ----
    #pragma unroll
    for (int t = 0; t < (MT * D) / NTHREADS; t++) {
        int lin = t * NTHREADS + tid;
        int r = lin >> 6;
        int d = lin & 63;
        float v = xin[(size_t)row0 * D + lin];
        *(ull*)&sx2[d * WX + 2 * r] = pack2(v, v);
    }
    __syncthreads();

    // ---- |x|^2 for the warp's 8 rows: lane L -> row (L&7), d-quarter (L>>3) ----
    float xn[8];
    {
        int r8 = lane & 7;
        int q  = lane >> 3;
        float s = 0.f;
        #pragma unroll
        for (int i = 0; i < 16; i++) {
            float v = sx2[(q * 16 + i) * WX + rb2 + 2 * r8];
            s = fmaf(v, v, s);
        }
        s += __shfl_xor_sync(0xffffffffu, s, 8);
        s += __shfl_xor_sync(0xffffffffu, s, 16);
        #pragma unroll
        for (int r = 0; r < 8; r++) xn[r] = __shfl_sync(0xffffffffu, s, r);
    }

    float bd[8];
    int   bi[8];
    #pragma unroll
    for (int i = 0; i < 8; i++) { bd[i] = 3.4e38f; bi[i] = 0; }

    const int c4 = tid & 3;          // code low 2 bits for the store phase
    const int ds = tid >> 2;         // dim 0..63 for the store phase

    // ---- chunk loop over codebook ----
    for (int ck = 0; ck < KCODES / KC; ck++) {
        const int kbase = ck * KC;
        __syncthreads();
        // transposed store, additive swizzle gs=(g+2d)&31.
        // store bank = 4*((3d+g)%8) + c4 over the warp -> all 32 banks distinct.
        #pragma unroll
        for (int g = 0; g < 32; g++) {
            int kc = (g << 2) | c4;
            int gs = (g + 2 * ds) & 31;
            sc[ds * WC + (gs << 2) + c4] = cb[(size_t)(kbase + kc) * D + ds];
        }
        // per-chunk code norms (cheap, hits L1/L2)
        if (tid < KC) {
            const float* c = cb + (size_t)(kbase + tid) * D;
            float s = 0.f;
            #pragma unroll
            for (int q = 0; q < D / 4; q++) {
                float4 v = *(const float4*)(c + 4 * q);
                s = fmaf(v.x, v.x, fmaf(v.y, v.y, fmaf(v.z, v.z, fmaf(v.w, v.w, s))));
            }
            scn[tid] = s;
        }
        __syncthreads();

        ull acc[8][2];
        #pragma unroll
        for (int r = 0; r < 8; r++) { acc[r][0] = 0ull; acc[r][1] = 0ull; }

        #pragma unroll 2
        for (int d = 0; d < D; d++) {
            // codes 4L..4L+3 at dim d: one LDS.128, 32 distinct lanes, swizzled
            const float* crow = sc + d * WC + ((((unsigned)(lane + 2 * d)) & 31) << 2);
            ulonglong2 cu = *(const ulonglong2*)crow;   // .x={c4L,c4L+1} .y={c4L+2,c4L+3}
            // warp's 8 dup'd rows at dim d: 4 broadcast LDS.128
            const float* xrow = sx2 + d * WX + rb2;
            ulonglong2 xA = *(const ulonglong2*)(xrow);      // {r0,r0},{r1,r1}
            ulonglong2 xB = *(const ulonglong2*)(xrow + 4);  // {r2,r2},{r3,r3}
            ulonglong2 xC = *(const ulonglong2*)(xrow + 8);
            ulonglong2 xD = *(const ulonglong2*)(xrow + 12);
            acc[0][0] = fma2(xA.x, cu.x, acc[0][0]);
            acc[0][1] = fma2(xA.x, cu.y, acc[0][1]);
            acc[1][0] = fma2(xA.y, cu.x, acc[1][0]);
            acc[1][1] = fma2(xA.y, cu.y, acc[1][1]);
            acc[2][0] = fma2(xB.x, cu.x, acc[2][0]);
            acc[2][1] = fma2(xB.x, cu.y, acc[2][1]);
            acc[3][0] = fma2(xB.y, cu.x, acc[3][0]);
            acc[3][1] = fma2(xB.y, cu.y, acc[3][1]);
            acc[4][0] = fma2(xC.x, cu.x, acc[4][0]);
            acc[4][1] = fma2(xC.x, cu.y, acc[4][1]);
            acc[5][0] = fma2(xC.y, cu.x, acc[5][0]);
            acc[5][1] = fma2(xC.y, cu.y, acc[5][1]);
            acc[6][0] = fma2(xD.x, cu.x, acc[6][0]);
            acc[6][1] = fma2(xD.x, cu.y, acc[6][1]);
            acc[7][0] = fma2(xD.y, cu.x, acc[7][0]);
            acc[7][1] = fma2(xD.y, cu.y, acc[7][1]);
        }

        // distances (reference add order) + running argmin.
        // per-thread visit order k-ascending: 4L,4L+1 then 4L+2,4L+3; strict <
        #pragma unroll
        for (int p = 0; p < 2; p++) {
            int   kp  = 4 * lane + 2 * p;
            int   k0  = kbase + kp;
            float cn0 = scn[kp];
            float cn1 = scn[kp + 1];
            #pragma unroll
            for (int r = 0; r < 8; r++) {
                float s0 = lo32(acc[r][p]);
                float s1 = hi32(acc[r][p]);
                float d0 = (xn[r] + cn0) - 2.f * s0;
                float d1 = (xn[r] + cn1) - 2.f * s1;
                if (d0 < bd[r]) { bd[r] = d0; bi[r] = k0; }
                if (d1 < bd[r]) { bd[r] = d1; bi[r] = k0 + 1; }
            }
        }
    }

    // ---- argmin reduce across the full warp (tie -> lower index) ----
    #pragma unroll
    for (int i = 0; i < 8; i++) {
        float d = bd[i];
        int   b = bi[i];
        #pragma unroll
        for (int off = 16; off >= 1; off >>= 1) {
            float od = __shfl_xor_sync(0xffffffffu, d, off);
            int   ob = __shfl_xor_sync(0xffffffffu, b, off);
            if (od < d || (od == d && ob < b)) { d = od; b = ob; }
        }
        bd[i] = d;
        bi[i] = b;
    }

    // ---- epilogue: tokens, quantized_st, loss & usage partials ----
    const int grow = row0 + warp * 8;
    if (lane < 8) {
        outt[grow + lane] = (float)bi[lane];
        atomicAdd(&g_counts[bi[lane]], 1);
    }
    float e_acc = 0.f, q_acc = 0.f;
    {
        int r   = lane >> 2;        // 0..7
        int seg = lane & 3;         // 16-float segment
        int row = grow + r;
        int b   = bi[r];
        #pragma unroll
        for (int t = 0; t < 4; t++) {
            int col = seg * 16 + t * 4;
            float4 q4 = *(const float4*)&cb[(size_t)b * D + col];
            float4 x4 = *(const float4*)&xin[(size_t)row * D + col];
            float t0 = q4.x - x4.x, t1 = q4.y - x4.y, t2 = q4.z - x4.z, t3 = q4.w - x4.w;
            float4 o;
            o.x = x4.x + t0; o.y = x4.y + t1; o.z = x4.z + t2; o.w = x4.w + t3;
            *(float4*)&outq[(size_t)row * D + col] = o;
            float e0 = o.x - x4.x, e1 = o.y - x4.y, e2 = o.z - x4.z, e3 = o.w - x4.w;
            e_acc += e0 * e0 + e1 * e1 + e2 * e2 + e3 * e3;
            q_acc += t0 * t0 + t1 * t1 + t2 * t2 + t3 * t3;
        }
    }
    #pragma unroll
    for (int off = 16; off >= 1; off >>= 1) {
        e_acc += __shfl_xor_sync(0xffffffffu, e_acc, off);
        q_acc += __shfl_xor_sync(0xffffffffu, q_acc, off);
    }
    if (lane == 0) {
        atomicAdd(&g_loss[0], e_acc);
        atomicAdd(&g_loss[1], q_acc);
    }

    // ---- last-block finalize (4 scalars) + scratch reset for next replay ----
    __threadfence();
    __syncthreads();
    if (tid == 0) {
        unsigned t = atomicAdd(&g_done, 1u);
        s_last = (t == gridDim.x - 1) ? 1 : 0;
    }
    __syncthreads();
    if (s_last) {
        float h = 0.f;
        for (int k = tid; k < KCODES; k += NTHREADS) {
            float p = (float)g_counts[k] * invN;
            h += p * logf(p + 1e-10f);
        }
        sx2[tid] = h;
        __syncthreads();
        for (int s = NTHREADS / 2; s > 0; s >>= 1) {
            if (tid < s) sx2[tid] += sx2[tid + s];
            __syncthreads();
        }
        if (tid == 0) {
            float Le = g_loss[0] * inv_ND;
            float Lq = g_loss[1] * inv_ND;
            float commitment = 0.25f * Le;       // COMMITMENT_COST
            outs[0] = commitment + Lq;           // vq_loss
            outs[1] = commitment;                // commitment_loss
            outs[2] = Lq;                        // codebook_loss
            outs[3] = expf(-sx2[0]);             // perplexity
            g_loss[0] = 0.f;
            g_loss[1] = 0.f;
            g_done = 0u;
        }
        __syncthreads();
        for (int k = tid; k < KCODES; k += NTHREADS) g_counts[k] = 0;
    }
}

extern "C" void kernel_launch(void* const* d_in, const int* in_sizes, int n_in,
                              void* d_out, int out_size) {
    const float* x  = (const float*)d_in[0];
    const float* cb = (const float*)d_in[1];
    float* out = (float*)d_out;

    const int ND = in_sizes[0];       // N * D
    const int N  = ND / D;            // 262144

    float* outq = out;                // quantized_st, ND floats
    float* outt = out + ND;           // tokens (as float), N floats
    float* outs = out + ND + N;       // 4 scalars

    const int smem_bytes = (2 * D * WX + KC) * (int)sizeof(float);  // ~66.5 KB
    cudaFuncSetAttribute(vq_fused, cudaFuncAttributeMaxDynamicSharedMemorySize, smem_bytes);

    vq_fused<<<N / MT, NTHREADS, smem_bytes>>>(x, cb, outq, outt, outs,
                                               1.f / (float)ND, 1.f / (float)N);
}